// round 2
// baseline (speedup 1.0000x reference)
#include <cuda_runtime.h>
#include <math.h>

#define NVEH 8192
#define NT   512
#define IND  12
#define U    20
#define VPC  32
#define TPB  (VPC*4)

// ---------------- activation helpers (accurate fast-path) ----------------
__device__ __forceinline__ float sigm(float x){
    float e = __expf(-x);                       // MUFU.EX2 based, ~2 ulp
    return __fdividef(1.0f, 1.0f + e);          // approx div, ~2^-21 rel
}
__device__ __forceinline__ float tanh_acc(float x){
    // tanh(x) = 2*sigmoid(2x) - 1
    float s = sigm(2.0f * x);
    return fmaf(2.0f, s, -1.0f);
}
__device__ __forceinline__ float nanfix(float x){
    // robust under fast-math: bit test for NaN
    unsigned u = __float_as_uint(x);
    return ((u & 0x7fffffffu) > 0x7f800000u) ? 1.0f : x;
}

__global__ __launch_bounds__(TPB)
void lstm_kernel(
    const float* __restrict__ lf,   // (8192,512,12)
    const float* __restrict__ tt,   // (8192,512)
    const float* __restrict__ hs,   // (2,8192,20)
    const float* __restrict__ Wk,   // (12,80)
    const float* __restrict__ Wr,   // (20,80)
    const float* __restrict__ bl,   // (80)
    const float* __restrict__ Wd,   // (20,10)
    const float* __restrict__ bd,   // (10)
    const float* __restrict__ Wlc,  // (10,3)
    const float* __restrict__ blc,  // (3)
    float* __restrict__ out)
{
    // Weights in shared; z-weights permuted so thread j's 20 columns are contiguous.
    // permuted index p = j*20 + g*5 + i  <->  original col = g*20 + 5*j + i
    __shared__ float sWk[12*80];
    __shared__ float sWr[20*80];
    __shared__ float sbl[80];
    __shared__ float sWd[200];
    __shared__ float sbd[10];
    __shared__ float sWlc[30];
    __shared__ float sblc[3];

    const int tid = threadIdx.x;
    for (int idx = tid; idx < 12*80; idx += TPB){
        int k = idx/80, p = idx%80;
        int j = p/20, r = p%20, g = r/5, i = r%5;
        sWk[idx] = Wk[k*80 + g*20 + 5*j + i];
    }
    for (int idx = tid; idx < 20*80; idx += TPB){
        int k = idx/80, p = idx%80;
        int j = p/20, r = p%20, g = r/5, i = r%5;
        sWr[idx] = Wr[k*80 + g*20 + 5*j + i];
    }
    for (int idx = tid; idx < 80; idx += TPB){
        int p = idx, j = p/20, r = p%20, g = r/5, i = r%5;
        sbl[idx] = bl[g*20 + 5*j + i];
    }
    for (int idx = tid; idx < 200; idx += TPB) sWd[idx]  = Wd[idx];
    for (int idx = tid; idx < 10;  idx += TPB) sbd[idx]  = bd[idx];
    for (int idx = tid; idx < 30;  idx += TPB) sWlc[idx] = Wlc[idx];
    for (int idx = tid; idx < 3;   idx += TPB) sblc[idx] = blc[idx];
    __syncthreads();

    const int j     = tid & 3;        // sub-thread within vehicle quad
    const int v     = blockIdx.x * VPC + (tid >> 2);
    const int lane  = tid & 31;
    const int lbase = lane & ~3;

    const float* lfv = lf + (size_t)v * NT * IND;
    const float* ttv = tt + (size_t)v * NT;
    float* outlc = out + (size_t)NVEH*NT + (size_t)v * NT * 3;
    const size_t H_BASE = (size_t)NVEH*NT + (size_t)NVEH*NT*3;       // 16777216
    const size_t C_BASE = H_BASE + (size_t)NVEH*U;                   // 16941056

    // state: this thread owns units u = 5*j + i, i in [0,5)
    float hn[5], c[5];
    #pragma unroll
    for (int i = 0; i < 5; i++){
        hn[i] = hs[(size_t)v*U + 5*j + i];
        c[i]  = hs[(size_t)NVEH*U + (size_t)v*U + 5*j + i];
    }

    const float* wkj = &sWk[20*j];
    const float* wrj = &sWr[20*j];

    #pragma unroll 1
    for (int t = 0; t < NT; t++){
        // ---- broadcast h_{t-1} across the quad (also used for dense of step t-1) ----
        float hf[20];
        #pragma unroll
        for (int s = 0; s < 4; s++)
            #pragma unroll
            for (int i = 0; i < 5; i++)
                hf[5*s+i] = __shfl_sync(0xffffffffu, hn[i], lbase + s);

        // ---- dense + lc for previous step (uses h_{t-1}) ----
        if (t > 0){
            // thread j computes d-cols: {j, 4+j} and (j<2) also {8+j}
            float dd[3];
            #pragma unroll
            for (int m = 0; m < 3; m++){
                int col = m*4 + j;
                if (m == 2) col = (j < 2) ? (8 + j) : 8;   // clamped, unused for j>=2
                float a = sbd[col];
                #pragma unroll
                for (int k = 0; k < U; k++) a = fmaf(hf[k], sWd[k*10 + col], a);
                dd[m] = fmaxf(a, 0.0f);
            }
            float dfull[10];
            #pragma unroll
            for (int cc = 0; cc < 10; cc++){
                int src  = (cc < 8) ? (cc & 3) : (cc - 8);
                int ridx = (cc < 8) ? (cc >> 2) : 2;
                dfull[cc] = __shfl_sync(0xffffffffu, dd[ridx], lbase + src);
            }
            if (j < 3){
                float acc = sblc[j];
                #pragma unroll
                for (int m = 0; m < 10; m++) acc = fmaf(dfull[m], sWlc[m*3 + j], acc);
                outlc[(size_t)(t-1)*3 + j] = acc;
            }
        }

        // ---- load + transform x_t (threads 0..2 of each quad load 4 floats each) ----
        float xq[4] = {0.f, 0.f, 0.f, 0.f};
        if (j < 3){
            const float4 e = *reinterpret_cast<const float4*>(lfv + (size_t)t*IND + 4*j);
            float pos = (j < 2) ? ttv[t] : 0.0f;
            if (j == 0){
                xq[0] = (e.x - pos) * 0.01f;
                xq[1] = (e.y - pos) * 0.01f;
                xq[2] = (e.z - pos) * 0.01f;
                xq[3] = (pos - e.w) * 0.01f;
            } else if (j == 1){
                xq[0] = (pos - e.x) * 0.01f;
                xq[1] = (pos - e.y) * 0.01f;
                xq[2] = e.z * 0.025f;
                xq[3] = e.w * 0.025f;
            } else {
                xq[0] = e.x * 0.025f;
                xq[1] = e.y * 0.025f;
                xq[2] = e.z * 0.025f;
                xq[3] = e.w * 0.025f;
            }
            #pragma unroll
            for (int m = 0; m < 4; m++) xq[m] = nanfix(xq[m]);
        }
        float x[12];
        #pragma unroll
        for (int s = 0; s < 3; s++)
            #pragma unroll
            for (int m = 0; m < 4; m++)
                x[4*s+m] = __shfl_sync(0xffffffffu, xq[m], lbase + s);

        // ---- z = x@Wk + h@Wr + b  (this thread's 20 permuted columns) ----
        float z[20];
        #pragma unroll
        for (int p = 0; p < 20; p++) z[p] = sbl[20*j + p];
        #pragma unroll
        for (int k = 0; k < IND; k++){
            float xk = x[k];
            const float* w = &wkj[k*80];
            #pragma unroll
            for (int p = 0; p < 20; p++) z[p] = fmaf(xk, w[p], z[p]);
        }
        #pragma unroll
        for (int k = 0; k < U; k++){
            float hk = hf[k];
            const float* w = &wrj[k*80];
            #pragma unroll
            for (int p = 0; p < 20; p++) z[p] = fmaf(hk, w[p], z[p]);
        }

        // ---- gates + state update (all local; p = g*5 + i) ----
        #pragma unroll
        for (int i = 0; i < 5; i++){
            float ai = sigm(z[i]);
            float af = sigm(z[5+i]);
            float ag = tanh_acc(z[10+i]);
            float ao = sigm(z[15+i]);
            float cn = fmaf(af, c[i], ai*ag);
            c[i]  = cn;
            hn[i] = ao * tanh_acc(cn);
        }
    }

    // ---- epilogue: dense/lc for t = NT-1, write final h and c ----
    {
        float hf[20];
        #pragma unroll
        for (int s = 0; s < 4; s++)
            #pragma unroll
            for (int i = 0; i < 5; i++)
                hf[5*s+i] = __shfl_sync(0xffffffffu, hn[i], lbase + s);

        float dd[3];
        #pragma unroll
        for (int m = 0; m < 3; m++){
            int col = m*4 + j;
            if (m == 2) col = (j < 2) ? (8 + j) : 8;
            float a = sbd[col];
            #pragma unroll
            for (int k = 0; k < U; k++) a = fmaf(hf[k], sWd[k*10 + col], a);
            dd[m] = fmaxf(a, 0.0f);
        }
        float dfull[10];
        #pragma unroll
        for (int cc = 0; cc < 10; cc++){
            int src  = (cc < 8) ? (cc & 3) : (cc - 8);
            int ridx = (cc < 8) ? (cc >> 2) : 2;
            dfull[cc] = __shfl_sync(0xffffffffu, dd[ridx], lbase + src);
        }
        if (j < 3){
            float acc = sblc[j];
            #pragma unroll
            for (int m = 0; m < 10; m++) acc = fmaf(dfull[m], sWlc[m*3 + j], acc);
            outlc[(size_t)(NT-1)*3 + j] = acc;
        }

        #pragma unroll
        for (int i = 0; i < 5; i++){
            out[H_BASE + (size_t)v*U + 5*j + i] = hn[i];
            out[C_BASE + (size_t)v*U + 5*j + i] = c[i];
        }
    }
}

extern "C" void kernel_launch(void* const* d_in, const int* in_sizes, int n_in,
                              void* d_out, int out_size)
{
    const float* lf  = (const float*)d_in[0];
    const float* tt  = (const float*)d_in[1];
    const float* hs  = (const float*)d_in[2];
    const float* Wk  = (const float*)d_in[3];
    const float* Wr  = (const float*)d_in[4];
    const float* bl  = (const float*)d_in[5];
    const float* Wd  = (const float*)d_in[6];
    const float* bd  = (const float*)d_in[7];
    const float* Wlc = (const float*)d_in[8];
    const float* blc = (const float*)d_in[9];
    float* out = (float*)d_out;

    // output region 0: exact copy of true_traj
    cudaMemcpyAsync(out, tt, (size_t)NVEH * NT * sizeof(float),
                    cudaMemcpyDeviceToDevice);

    lstm_kernel<<<NVEH / VPC, TPB>>>(lf, tt, hs, Wk, Wr, bl, Wd, bd, Wlc, blc, out);
}

// round 3
// speedup vs baseline: 1.2866x; 1.2866x over previous
#include <cuda_runtime.h>
#include <math.h>

#define NVEH 8192
#define NT   512
#define IND  12
#define U    20
#define VPC  32      // vehicles per CTA (one per lane)
#define TPB  128     // 4 warps; warp w owns units 5w..5w+4 (all 4 gates)

typedef unsigned long long ull;

// ---------------- packed f32x2 helpers (sm_103a) ----------------
__device__ __forceinline__ ull fma2(ull w, ull m, ull acc){
    ull d;
    asm("fma.rn.f32x2 %0, %1, %2, %3;" : "=l"(d) : "l"(w), "l"(m), "l"(acc));
    return d;
}
__device__ __forceinline__ ull splat2(float x){
    ull d; asm("mov.b64 %0, {%1, %1};" : "=l"(d) : "f"(x)); return d;
}
__device__ __forceinline__ ull pack2(float a, float b){
    ull d; asm("mov.b64 %0, {%1, %2};" : "=l"(d) : "f"(a), "f"(b)); return d;
}
__device__ __forceinline__ float2 unpack2(ull a){
    float2 r; asm("mov.b64 {%0, %1}, %2;" : "=f"(r.x), "=f"(r.y) : "l"(a)); return r;
}

// ---------------- activations (accurate fast-path) ----------------
__device__ __forceinline__ float sigm(float x){
    float e = __expf(-x);
    return __fdividef(1.0f, 1.0f + e);
}
__device__ __forceinline__ float tanh_acc(float x){
    float s = sigm(2.0f * x);
    return fmaf(2.0f, s, -1.0f);
}
__device__ __forceinline__ float nanfix(float x){
    unsigned u = __float_as_uint(x);
    return ((u & 0x7fffffffu) > 0x7f800000u) ? 1.0f : x;
}

__global__ __launch_bounds__(TPB)
void lstm_kernel(
    const float* __restrict__ lf,   // (8192,512,12)
    const float* __restrict__ tt,   // (8192,512)
    const float* __restrict__ hs,   // (2,8192,20)
    const float* __restrict__ Wk,   // (12,80)
    const float* __restrict__ Wr,   // (20,80)
    const float* __restrict__ bl,   // (80)
    const float* __restrict__ Wd,   // (20,10)
    const float* __restrict__ bd,   // (10)
    const float* __restrict__ Wlc,  // (10,3)
    const float* __restrict__ blc,  // (3)
    float* __restrict__ out)
{
    // combined z-weights (rows 0..11 = Wk, 12..31 = Wr), columns permuted:
    // P = w*20 + g*5 + i  <->  original col = g*20 + (w*5 + i)
    __shared__ float sZW[32*80];
    __shared__ float sbl[80];
    __shared__ float sWdT[10*20];   // transposed: [col][k]
    __shared__ float sbd[10];
    __shared__ float sWlc[30];
    __shared__ float sblc[3];
    __shared__ float sH[2][VPC*21]; // double-buffered h, stride 21 (coprime w/ 32)

    const int tid = threadIdx.x;
    for (int idx = tid; idx < 32*80; idx += TPB){
        int k = idx/80, P = idx%80;
        int w = P/20, r = P%20, g = r/5, i = r%5;
        int oc = g*20 + w*5 + i;
        sZW[idx] = (k < IND) ? Wk[k*80 + oc] : Wr[(k-IND)*80 + oc];
    }
    for (int idx = tid; idx < 80; idx += TPB){
        int w = idx/20, r = idx%20, g = r/5, i = r%5;
        sbl[idx] = bl[g*20 + w*5 + i];
    }
    for (int idx = tid; idx < 200; idx += TPB){
        int c = idx/20, k = idx%20;
        sWdT[idx] = Wd[k*10 + c];
    }
    for (int idx = tid; idx < 10; idx += TPB) sbd[idx]  = bd[idx];
    for (int idx = tid; idx < 30; idx += TPB) sWlc[idx] = Wlc[idx];
    for (int idx = tid; idx < 3;  idx += TPB) sblc[idx] = blc[idx];
    // initial h into buffer 0
    for (int idx = tid; idx < VPC*U; idx += TPB){
        int l = idx/U, k = idx%U;
        sH[0][l*21 + k] = hs[((size_t)blockIdx.x*VPC + l)*U + k];
    }
    __syncthreads();

    const int w = tid >> 5;            // warp id = unit-slice
    const int l = tid & 31;            // lane = vehicle within CTA
    const int v = blockIdx.x*VPC + l;

    const float* lfv = lf + (size_t)v * NT * IND;
    const float* ttv = tt + (size_t)v * NT;
    float* outlc = out + (size_t)NVEH*NT + (size_t)v * NT * 3;
    const size_t H_BASE = (size_t)NVEH*NT + (size_t)NVEH*NT*3;
    const size_t C_BASE = H_BASE + (size_t)NVEH*U;

    // cell state for this warp's 5 units of vehicle l
    float c5[5], hn[5];
    #pragma unroll
    for (int i = 0; i < 5; i++){
        c5[i] = hs[(size_t)NVEH*U + (size_t)v*U + w*5 + i];
        hn[i] = 0.0f;
    }

    const float* swb = &sZW[w*20];     // warp's 20-col slice; +k*80 per row
    // biases resident in registers (constant over t)
    ull bq[10];
    {
        const ulonglong2* b2 = reinterpret_cast<const ulonglong2*>(&sbl[w*20]);
        #pragma unroll
        for (int p = 0; p < 5; p++){ ulonglong2 bv = b2[p]; bq[2*p] = bv.x; bq[2*p+1] = bv.y; }
    }

    #pragma unroll 1
    for (int t = 0; t < NT; t++){
        const float* bufP = sH[t & 1];
        float* bufC = sH[(t & 1) ^ 1];

        // ---- load + transform x_t for own vehicle ----
        const float4* xe = reinterpret_cast<const float4*>(lfv + (size_t)t * IND);
        float4 e0 = xe[0], e1 = xe[1], e2 = xe[2];
        float pos = ttv[t];
        float x[12];
        x[0] = (e0.x - pos) * 0.01f;
        x[1] = (e0.y - pos) * 0.01f;
        x[2] = (e0.z - pos) * 0.01f;
        x[3] = (pos - e0.w) * 0.01f;
        x[4] = (pos - e1.x) * 0.01f;
        x[5] = (pos - e1.y) * 0.01f;
        x[6] = e1.z * 0.025f;
        x[7] = e1.w * 0.025f;
        x[8] = e2.x * 0.025f;
        x[9] = e2.y * 0.025f;
        x[10] = e2.z * 0.025f;
        x[11] = e2.w * 0.025f;
        #pragma unroll
        for (int m = 0; m < 12; m++) x[m] = nanfix(x[m]);

        // ---- z = [x;h] @ W + b on this warp's 20 columns (f32x2 packed) ----
        union { ull q[10]; float s[20]; } Z;
        #pragma unroll
        for (int p = 0; p < 10; p++) Z.q[p] = bq[p];

        #pragma unroll
        for (int k = 0; k < IND; k++){
            ull m = splat2(x[k]);
            const ulonglong2* wr = reinterpret_cast<const ulonglong2*>(swb + k*80);
            #pragma unroll
            for (int p = 0; p < 5; p++){
                ulonglong2 wv = wr[p];            // uniform-address LDS.128 broadcast
                Z.q[2*p]   = fma2(wv.x, m, Z.q[2*p]);
                Z.q[2*p+1] = fma2(wv.y, m, Z.q[2*p+1]);
            }
        }
        const float* hrow = &bufP[l*21];
        #pragma unroll
        for (int k = 0; k < U; k++){
            ull m = splat2(hrow[k]);
            const ulonglong2* wr = reinterpret_cast<const ulonglong2*>(swb + (IND+k)*80);
            #pragma unroll
            for (int p = 0; p < 5; p++){
                ulonglong2 wv = wr[p];
                Z.q[2*p]   = fma2(wv.x, m, Z.q[2*p]);
                Z.q[2*p+1] = fma2(wv.y, m, Z.q[2*p+1]);
            }
        }

        // ---- gates (slice layout: s[g*5+i]) ----
        #pragma unroll
        for (int i = 0; i < 5; i++){
            float ai = sigm(Z.s[i]);
            float af = sigm(Z.s[5+i]);
            float ag = tanh_acc(Z.s[10+i]);
            float ao = sigm(Z.s[15+i]);
            float cn = fmaf(af, c5[i], ai*ag);
            c5[i]  = cn;
            hn[i]  = ao * tanh_acc(cn);
        }

        // ---- publish h_t ----
        #pragma unroll
        for (int i = 0; i < 5; i++) bufC[l*21 + w*5 + i] = hn[i];
        __syncthreads();

        // ---- dense(10)+relu + lc(3), duplicated across warps; warp0 stores ----
        ull hq[10];
        {
            const float* hc = &bufC[l*21];
            #pragma unroll
            for (int p = 0; p < 10; p++) hq[p] = pack2(hc[2*p], hc[2*p+1]);
        }
        float d[10];
        #pragma unroll
        for (int cc = 0; cc < 10; cc++){
            const ulonglong2* wd = reinterpret_cast<const ulonglong2*>(&sWdT[cc*20]);
            ull a = pack2(sbd[cc], 0.0f);
            #pragma unroll
            for (int p = 0; p < 5; p++){
                ulonglong2 wv = wd[p];
                a = fma2(wv.x, hq[2*p],   a);
                a = fma2(wv.y, hq[2*p+1], a);
            }
            float2 ur = unpack2(a);
            d[cc] = fmaxf(ur.x + ur.y, 0.0f);
        }
        if (w == 0){
            #pragma unroll
            for (int o = 0; o < 3; o++){
                float acc = sblc[o];
                #pragma unroll
                for (int m2 = 0; m2 < 10; m2++) acc = fmaf(d[m2], sWlc[m2*3 + o], acc);
                outlc[(size_t)t*3 + o] = acc;
            }
        }
    }

    // ---- final state ----
    #pragma unroll
    for (int i = 0; i < 5; i++){
        out[H_BASE + (size_t)v*U + w*5 + i] = hn[i];
        out[C_BASE + (size_t)v*U + w*5 + i] = c5[i];
    }
}

extern "C" void kernel_launch(void* const* d_in, const int* in_sizes, int n_in,
                              void* d_out, int out_size)
{
    const float* lf  = (const float*)d_in[0];
    const float* tt  = (const float*)d_in[1];
    const float* hs  = (const float*)d_in[2];
    const float* Wk  = (const float*)d_in[3];
    const float* Wr  = (const float*)d_in[4];
    const float* bl  = (const float*)d_in[5];
    const float* Wd  = (const float*)d_in[6];
    const float* bd  = (const float*)d_in[7];
    const float* Wlc = (const float*)d_in[8];
    const float* blc = (const float*)d_in[9];
    float* out = (float*)d_out;

    // output region 0: exact copy of true_traj
    cudaMemcpyAsync(out, tt, (size_t)NVEH * NT * sizeof(float),
                    cudaMemcpyDeviceToDevice);

    lstm_kernel<<<NVEH / VPC, TPB>>>(lf, tt, hs, Wk, Wr, bl, Wd, bd, Wlc, blc, out);
}